// round 15
// baseline (speedup 1.0000x reference)
#include <cuda_runtime.h>
#include <cstdint>

// 2-bit quantized embedding lookup — TMA bulk-store probe.
// Decode into a 32KB smem tile per block (64 tokens x 512B), then one
// cp.async.bulk.global.shared::cta (UBLKCP) per block pushes the tile to
// GMEM via the async-proxy/TMA path instead of per-warp STG through LSU/L1.
// Rationale: four STG-based variants all pin at ~24-25us with every pipe
// <60% and tma=0%; this moves the 134MB store stream off the LSU path.
//
// ids: [262144] (int32 OR int64, runtime-detected in-warp), bit_arr: [3.2M]
// int32, codebook: [4] float. Token's 128 codes = 8 aligned int32 words at
// bit_arr[tok*8]. Lane l owns dims 4l..4l+3; warp handles 8 tokens (MLP=8).

#define TPW 8              // tokens per warp
#define WARPS_PER_BLOCK 8  // 256 threads
#define TOK_PER_BLOCK (TPW * WARPS_PER_BLOCK)          // 64
#define TILE_BYTES (TOK_PER_BLOCK * 128 * 4)           // 32768

__device__ __forceinline__ float4 decode16(unsigned b,
                                           float c0, float c1, float c2, float c3)
{
    float4 v;
    {
        unsigned code = b & 3u;
        float a = (code & 1u) ? c1 : c0;
        float d = (code & 1u) ? c3 : c2;
        v.x = (code & 2u) ? d : a;
    }
    {
        unsigned code = (b >> 2) & 3u;
        float a = (code & 1u) ? c1 : c0;
        float d = (code & 1u) ? c3 : c2;
        v.y = (code & 2u) ? d : a;
    }
    {
        unsigned code = (b >> 4) & 3u;
        float a = (code & 1u) ? c1 : c0;
        float d = (code & 1u) ? c3 : c2;
        v.z = (code & 2u) ? d : a;
    }
    {
        unsigned code = (b >> 6) & 3u;
        float a = (code & 1u) ? c1 : c0;
        float d = (code & 1u) ? c3 : c2;
        v.w = (code & 2u) ? d : a;
    }
    return v;
}

__global__ void __launch_bounds__(256) embed2b_kernel(
    const unsigned* __restrict__ idw,   // ids viewed as 32-bit words
    const unsigned* __restrict__ bits,
    const float*    __restrict__ cb,
    float4*         __restrict__ out,
    int n_tokens)
{
    __shared__ float4 tile[TOK_PER_BLOCK * 32];        // 32KB staging tile

    int lane  = threadIdx.x & 31;
    int wid   = threadIdx.x >> 5;
    int bbase = blockIdx.x * TOK_PER_BLOCK;            // first token of block
    int wbase = bbase + wid * TPW;                     // first token of warp

    // ---- in-warp id-dtype detection (2 cache lines, broadcast hits) ----
    // int64 ids (nonneg < 2^31): odd 32-bit words 1..63 all zero.
    // int32 ids: 32 random ids all zero w.p. ~(2.5e-6)^32 ~ 0. Deterministic.
    unsigned oddw = __ldg(idw + 2 * lane + 1);
    int stride = __any_sync(0xffffffffu, oddw != 0u) ? 1 : 2;

    float c0 = __ldg(cb + 0);
    float c1 = __ldg(cb + 1);
    float c2 = __ldg(cb + 2);
    float c3 = __ldg(cb + 3);

    int wsel = lane >> 2;               // which packed word this lane needs
    int bsh  = (lane & 3) * 8;          // byte shift within that word

    if (bbase + TOK_PER_BLOCK <= n_tokens) {
        // ---- fast path: full 64-token block -> smem tile -> bulk store ----
        unsigned myid = __ldg(idw + (size_t)(wbase + (lane & (TPW - 1))) * stride);

        unsigned w[TPW];
        #pragma unroll
        for (int t = 0; t < TPW; t++) {         // 8 independent loads, MLP=8
            unsigned tok = __shfl_sync(0xffffffffu, myid, t, TPW);
            w[t] = __ldg(bits + tok * 8u + wsel);
        }

        #pragma unroll
        for (int t = 0; t < TPW; t++) {
            float4 v = decode16(w[t] >> bsh, c0, c1, c2, c3);
            tile[(wid * TPW + t) * 32 + lane] = v;      // conflict-free STS.128
        }

        // order generic smem writes before async-proxy read, then bulk copy
        __syncthreads();
        asm volatile("fence.proxy.async.shared::cta;" ::: "memory");
        if (threadIdx.x == 0) {
            unsigned saddr;
            asm("{ .reg .u64 t; cvta.to.shared.u64 t, %1; cvt.u32.u64 %0, t; }"
                : "=r"(saddr) : "l"(tile));
            const float4* dst = out + (size_t)bbase * 32;
            asm volatile(
                "cp.async.bulk.global.shared::cta.bulk_group [%0], [%1], %2;"
                :: "l"(dst), "r"(saddr), "n"(TILE_BYTES) : "memory");
            asm volatile("cp.async.bulk.commit_group;" ::: "memory");
            asm volatile("cp.async.bulk.wait_group 0;" ::: "memory");
        }
    } else {
        // ---- tail block: proven direct-STG path ----
        for (int t = 0; t < TPW && wbase + t < n_tokens; t++) {
            unsigned tok = __ldg(idw + (size_t)(wbase + t) * stride);
            unsigned wv  = __ldg(bits + tok * 8u + wsel);
            float4 v = decode16(wv >> bsh, c0, c1, c2, c3);
            out[(size_t)(wbase + t) * 32 + lane] = v;
        }
    }
}

extern "C" void kernel_launch(void* const* d_in, const int* in_sizes, int n_in,
                              void* d_out, int out_size)
{
    const unsigned* idw  = (const unsigned*)d_in[0];  // ids (int32 or int64)
    const unsigned* bits = (const unsigned*)d_in[1];  // packed 2-bit codes
    const float*    cb   = (const float*)d_in[2];     // 4-entry codebook
    float*          out  = (float*)d_out;             // [N, 128] fp32

    int n_tokens = in_sizes[0];                        // 64*4096 = 262144

    int grid = (n_tokens + TOK_PER_BLOCK - 1) / TOK_PER_BLOCK;   // 4096 exact
    embed2b_kernel<<<grid, 256>>>(idw, bits, cb, (float4*)out, n_tokens);
}

// round 16
// speedup vs baseline: 1.1831x; 1.1831x over previous
#include <cuda_runtime.h>
#include <cstdint>

// 2-bit quantized embedding lookup — FINAL configuration (session best, R14:
// total 24.64us, main 24.5us, occ 81.7%, regs 32).
//
// Session evidence trail:
//   R6  dim-strided stores: L1 wavefront-bound (67%) .......... 39.7us main
//   R7  warp-coalesced STG.128 (4 full lines/warp-store) ...... 40.1 -> latency-bound
//   R9  MLP=8 token-group gathers ............................. 24.9us main
//   R10 MLP=16 + __stcs ....................................... neutral
//   R11 persistent grid + 2-deep pipeline ..................... worse (27.8)
//   R13 STG.256 pair stores ................................... neutral (25.1)
//   R15 TMA bulk-store (cp.async.bulk, smem staging) .......... neutral (24.64)
// Five structural variants pin at 24.2-25.1us: the kernel sits at the
// path-independent LTS store ceiling (B300: ~6300 B/cyc, LDG.cv == TMA) for
// the 134MB output stream. This is the structural floor.
//
// ids: [262144] (int32 OR int64, runtime-detected in-warp), bit_arr: [3.2M]
// int32, codebook: [4] float. Token's 128 codes = 8 aligned int32 words at
// bit_arr[tok*8].
//
// One warp per 8-token group: lane l loads id[base+(l&7)] (one 32B segment),
// shfl(width=8) broadcasts; 8 independent 32B-sector gathers (MLP=8); decode
// branch-free (2-level select); 8 coalesced 512B STG.128.CS bursts (4 full
// 128B lines each; evict-first keeps the 12.8MB bit_arr L2-resident).
// Lane l owns dims 4l..4l+3 of each token.

#define TPW 8   // tokens per warp

__device__ __forceinline__ float4 decode16(unsigned b,
                                           float c0, float c1, float c2, float c3)
{
    float4 v;
    {
        unsigned code = b & 3u;
        float a = (code & 1u) ? c1 : c0;
        float d = (code & 1u) ? c3 : c2;
        v.x = (code & 2u) ? d : a;
    }
    {
        unsigned code = (b >> 2) & 3u;
        float a = (code & 1u) ? c1 : c0;
        float d = (code & 1u) ? c3 : c2;
        v.y = (code & 2u) ? d : a;
    }
    {
        unsigned code = (b >> 4) & 3u;
        float a = (code & 1u) ? c1 : c0;
        float d = (code & 1u) ? c3 : c2;
        v.z = (code & 2u) ? d : a;
    }
    {
        unsigned code = (b >> 6) & 3u;
        float a = (code & 1u) ? c1 : c0;
        float d = (code & 1u) ? c3 : c2;
        v.w = (code & 2u) ? d : a;
    }
    return v;
}

__global__ void __launch_bounds__(256) embed2b_kernel(
    const unsigned* __restrict__ idw,   // ids viewed as 32-bit words
    const unsigned* __restrict__ bits,
    const float*    __restrict__ cb,
    float4*         __restrict__ out,
    int n_tokens)
{
    int gt    = blockIdx.x * blockDim.x + threadIdx.x;
    int lane  = threadIdx.x & 31;
    int wbase = (gt >> 5) * TPW;        // first token of this warp

    // ---- in-warp id-dtype detection (2 cache lines, broadcast hits) ----
    // int64 ids (nonneg < 2^31): odd 32-bit words 1..63 all zero.
    // int32 ids: 32 random ids all zero w.p. ~(2.5e-6)^32 ~ 0. Deterministic.
    unsigned oddw = __ldg(idw + 2 * lane + 1);
    int stride = __any_sync(0xffffffffu, oddw != 0u) ? 1 : 2;

    if (wbase >= n_tokens) return;

    float c0 = __ldg(cb + 0);
    float c1 = __ldg(cb + 1);
    float c2 = __ldg(cb + 2);
    float c3 = __ldg(cb + 3);

    int wsel = lane >> 2;               // which packed word this lane needs
    int bsh  = (lane & 3) * 8;          // byte shift within that word

    if (wbase + TPW <= n_tokens) {
        // ---- fast path: full group of 8 tokens ----
        // lane l holds id of token wbase + (l&7); low word = full value (LE)
        unsigned myid = __ldg(idw + (size_t)(wbase + (lane & (TPW - 1))) * stride);

        unsigned w[TPW];
        #pragma unroll
        for (int t = 0; t < TPW; t++) {         // 8 independent loads, MLP=8
            unsigned tok = __shfl_sync(0xffffffffu, myid, t, TPW);
            w[t] = __ldg(bits + tok * 8u + wsel);
        }

        #pragma unroll
        for (int t = 0; t < TPW; t++) {
            float4 v = decode16(w[t] >> bsh, c0, c1, c2, c3);
            // 4 full 128B lines per warp-store; evict-first in L2
            __stcs(out + (size_t)(wbase + t) * 32 + lane, v);
        }
    } else {
        // ---- tail: per-token ----
        for (int t = 0; t < TPW && wbase + t < n_tokens; t++) {
            unsigned tok = __ldg(idw + (size_t)(wbase + t) * stride);
            unsigned wv  = __ldg(bits + tok * 8u + wsel);
            float4 v = decode16(wv >> bsh, c0, c1, c2, c3);
            __stcs(out + (size_t)(wbase + t) * 32 + lane, v);
        }
    }
}

extern "C" void kernel_launch(void* const* d_in, const int* in_sizes, int n_in,
                              void* d_out, int out_size)
{
    const unsigned* idw  = (const unsigned*)d_in[0];  // ids (int32 or int64)
    const unsigned* bits = (const unsigned*)d_in[1];  // packed 2-bit codes
    const float*    cb   = (const float*)d_in[2];     // 4-entry codebook
    float*          out  = (float*)d_out;             // [N, 128] fp32

    int n_tokens = in_sizes[0];                        // 64*4096 = 262144

    int warps  = (n_tokens + TPW - 1) / TPW;
    long long total_threads = (long long)warps * 32;
    int block = 256;
    int grid = (int)((total_threads + block - 1) / block);
    embed2b_kernel<<<grid, block>>>(idw, bits, cb, (float4*)out, n_tokens);
}